// round 6
// baseline (speedup 1.0000x reference)
#include <cuda_runtime.h>
#include <cuda_fp16.h>
#include <cstdint>

#define NN 100000
#define EE 1600000
#define TOTE (NN + EE)

// ---------------- static device scratch (allocation-free, zero-init) ----------------
__device__ int                g_rowptr[NN + 1];
__device__ int                g_cnt[NN];          // histogram; reset by k_scan for next replay
__device__ int                g_cur[NN];          // scatter cursor
__device__ float              g_dis[NN];          // rsqrt(deg)
__device__ float2             g_axw[NN];          // {A_hat x, A_hat 1} per node (atomic-built)
__device__ unsigned long long g_edge[TOTE];       // packed {src(int32) | normbits<<32}
__device__ uint2              g_bufA[NN * 8];     // fp16 feature rows, 64B/node
__device__ uint2              g_bufB[NN * 8];
__device__ uint2              g_bufC[NN * 8];

__device__ __forceinline__ unsigned long long pack_edge(int c, float w) {
    return (unsigned long long)(unsigned)c |
           ((unsigned long long)__float_as_uint(w) << 32);
}

__device__ __forceinline__ uint32_t packh2(float a, float b) {
    __half2 h = __floats2half2_rn(a, b);
    return *reinterpret_cast<uint32_t*>(&h);
}

__device__ __forceinline__ void mma16816(float c[4], const uint32_t a[4], const uint32_t b[2]) {
    asm volatile("mma.sync.aligned.m16n8k16.row.col.f32.f16.f16.f32 "
                 "{%0,%1,%2,%3},{%4,%5,%6,%7},{%8,%9},{%0,%1,%2,%3};"
                 : "+f"(c[0]), "+f"(c[1]), "+f"(c[2]), "+f"(c[3])
                 : "r"(a[0]), "r"(a[1]), "r"(a[2]), "r"(a[3]), "r"(b[0]), "r"(b[1]));
}

// ---------------- preprocessing (3 launches so conv1 is launch #4) ----------------
__global__ void k_hist(const int* __restrict__ ei, int E) {
    int e = blockIdx.x * blockDim.x + threadIdx.x;
    if (e < E) atomicAdd(&g_cnt[ei[E + e]], 1);
}

__global__ void k_scan(const float* __restrict__ x, int n) {
    __shared__ int warpsum[32];
    __shared__ int chunkbase;
    const int tid = threadIdx.x, lane = tid & 31, wid = tid >> 5;
    if (tid == 0) chunkbase = 0;
    __syncthreads();
    for (int base = 0; base < n; base += 1024) {
        int i = base + tid;
        int ecnt = (i < n) ? g_cnt[i] : 0;
        if (i < n) g_cnt[i] = 0;                   // reset for next replay
        int v = ecnt + 1;                          // + self-loop
        int s = v;
#pragma unroll
        for (int d = 1; d < 32; d <<= 1) {
            int t = __shfl_up_sync(0xffffffffu, s, d);
            if (lane >= d) s += t;
        }
        if (lane == 31) warpsum[wid] = s;
        __syncthreads();
        if (wid == 0) {
            int ws = warpsum[lane];
#pragma unroll
            for (int d = 1; d < 32; d <<= 1) {
                int t = __shfl_up_sync(0xffffffffu, ws, d);
                if (lane >= d) ws += t;
            }
            warpsum[lane] = ws;
        }
        __syncthreads();
        int excl = chunkbase + s - v + (wid ? warpsum[wid - 1] : 0);
        if (i < n) {
            g_rowptr[i] = excl;
            float dv = rsqrtf((float)v);
            float dvdv = dv * dv;
            g_dis[i] = dv;
            g_edge[excl] = pack_edge(i, dvdv);     // self-loop edge first in row
            g_cur[i] = excl + 1;
            g_axw[i] = make_float2(dvdv * __ldg(&x[i]), dvdv);  // self-loop seed
        }
        __syncthreads();
        if (tid == 0) chunkbase += warpsum[31];
        __syncthreads();
    }
    if (tid == 0) g_rowptr[n] = chunkbase;
}

__global__ void k_scatter_pre(const int* __restrict__ ei, int E,
                              const float* __restrict__ x, const float* __restrict__ y,
                              const float* __restrict__ fc1W, const float* __restrict__ fc1b,
                              const float* __restrict__ fc2W, const float* __restrict__ fc2b,
                              float* __restrict__ out, int n) {
    __shared__ float s1W[32], s1b[32], s2W[32 * 26], s2b[26];
    for (int i = threadIdx.x; i < 32; i += blockDim.x) { s1W[i] = fc1W[i]; s1b[i] = fc1b[i]; }
    for (int i = threadIdx.x; i < 32 * 26; i += blockDim.x) s2W[i] = fc2W[i];
    for (int i = threadIdx.x; i < 26; i += blockDim.x) s2b[i] = fc2b[i];
    __syncthreads();
    int total = n + E;
    int stride = gridDim.x * blockDim.x;
    for (int g = blockIdx.x * blockDim.x + threadIdx.x; g < total; g += stride) {
        if (g < n) {
            int i = g;
            float y0 = y[i];
            out[i] = y0;
            float h0[32];
#pragma unroll
            for (int j = 0; j < 32; j++) h0[j] = fmaxf(fmaf(y0, s1W[j], s1b[j]), 0.f);
            __align__(8) __half hrow[32];
            for (int j = 0; j < 26; j++) {
                float s = s2b[j];
#pragma unroll
                for (int k = 0; k < 32; k++) s = fmaf(h0[k], s2W[k * 26 + j], s);
                hrow[j] = __float2half(fmaxf(s, 0.f));
            }
#pragma unroll
            for (int j = 26; j < 32; j++) hrow[j] = __float2half(0.f);
            const uint2* hr = reinterpret_cast<const uint2*>(hrow);
#pragma unroll
            for (int q = 0; q < 8; q++) g_bufA[i * 8 + q] = hr[q];
        } else {
            int e = g - n;
            int s = ei[e];
            int d = ei[E + e];
            float w = g_dis[s] * g_dis[d];
            int pos = atomicAdd(&g_cur[d], 1);
            g_edge[pos] = pack_edge(s, w);
            atomicAdd(&g_axw[d].x, w * __ldg(&x[s]));
            atomicAdd(&g_axw[d].y, w);
        }
    }
}

// ---------------- fused GCN conv: 16-node batches, HMMA epilogue ----------------
// MODE 1: agg cols 26/27 carry (A_hat x, A_hat 1 * t); W~ rows 26/27 = folded wx/wt.
// MODE 2: plain 32 -> 32.
// MODE 3: 32 -> 26 (cols padded 0) + fused fc3/relu/fc4 head via second MMA chain.
template <int MODE>
__global__ __launch_bounds__(128)
void k_conv(const float* __restrict__ W, const float* __restrict__ B,
            const float* __restrict__ f3W, const float* __restrict__ f3b,
            const float* __restrict__ f4W, const float* __restrict__ f4b,
            const float* __restrict__ tarr, int trow,
            float* __restrict__ out, int n) {
    constexpr int OUT = (MODE == 3) ? 26 : 32;

    __shared__ __align__(16) __half sWt[32 * 40];   // W~ fp16, rows padded to 40 halves (80B)
    __shared__ __align__(16) __half sW2[32 * 40];   // fc3 padded (MODE 3 only)
    __shared__ __align__(16) __half sA[4][16 * 40]; // per-warp 16x32 agg tiles (1280B each)
    __shared__ float  sb[32];
    __shared__ float  sb3[32];
    __shared__ float  sf4[32];
    __shared__ float  sf4b;

    const int tid = threadIdx.x, lane = tid & 31, w = tid >> 5;

    for (int i = tid; i < 32 * 32; i += blockDim.x) {
        int k = i >> 5, j = i & 31;
        float v;
        if constexpr (MODE == 1) {
            if (k < 26)       v = W[k * 32 + j];
            else if (k == 26) v = W[26 * 32 + j] + W[27 * 32 + j] + W[28 * 32 + j];
            else if (k == 27) v = W[29 * 32 + j] + W[30 * 32 + j] + W[31 * 32 + j];
            else              v = 0.f;
        } else if constexpr (MODE == 2) {
            v = W[k * 32 + j];
        } else {
            v = (j < 26) ? W[k * 26 + j] : 0.f;
        }
        sWt[k * 40 + j] = __float2half(v);
        if constexpr (MODE == 3)
            sW2[k * 40 + j] = __float2half((k < 26) ? f3W[k * 32 + j] : 0.f);
    }
    for (int i = tid; i < 32; i += blockDim.x) {
        sb[i] = (i < OUT) ? B[i] : 0.f;
        if constexpr (MODE == 3) { sb3[i] = f3b[i]; sf4[i] = f4W[i]; }
    }
    if constexpr (MODE == 3) { if (tid == 0) sf4b = f4b[0]; }
    __syncthreads();

    // persistent B fragments: bf[kstep][ntile][2]
    uint32_t bf[2][4][2];
    uint32_t bf2[2][4][2];
    {
        int r = lane & 15;
#pragma unroll
        for (int s = 0; s < 2; s++)
#pragma unroll
            for (int t = 0; t < 4; t++) {
                uint32_t addr = (uint32_t)__cvta_generic_to_shared(&sWt[(s * 16 + r) * 40 + t * 8]);
                asm volatile("ldmatrix.sync.aligned.m8n8.x2.trans.shared.b16 {%0,%1},[%2];"
                             : "=r"(bf[s][t][0]), "=r"(bf[s][t][1]) : "r"(addr));
                if constexpr (MODE == 3) {
                    uint32_t a2 = (uint32_t)__cvta_generic_to_shared(&sW2[(s * 16 + r) * 40 + t * 8]);
                    asm volatile("ldmatrix.sync.aligned.m8n8.x2.trans.shared.b16 {%0,%1},[%2];"
                                 : "=r"(bf2[s][t][0]), "=r"(bf2[s][t][1]) : "r"(a2));
                }
            }
    }

    const int tig = lane & 3, grp = lane >> 2;
    float biasr[8];
#pragma unroll
    for (int t = 0; t < 4; t++) {
        biasr[t * 2]     = sb[t * 8 + tig * 2];
        biasr[t * 2 + 1] = sb[t * 8 + tig * 2 + 1];
    }
    float b3r[8], wf4[8], b4 = 0.f;
    if constexpr (MODE == 3) {
#pragma unroll
        for (int t = 0; t < 4; t++) {
            b3r[t * 2]     = sb3[t * 8 + tig * 2];
            b3r[t * 2 + 1] = sb3[t * 8 + tig * 2 + 1];
            wf4[t * 2]     = sf4[t * 8 + tig * 2];
            wf4[t * 2 + 1] = sf4[t * 8 + tig * 2 + 1];
        }
        b4 = sf4b;
    }

    const uint2* __restrict__ hin  = (MODE == 1) ? g_bufA : ((MODE == 2) ? g_bufB : g_bufC);
    uint2* __restrict__       hout = (MODE == 1) ? g_bufB : ((MODE == 2) ? g_bufC : g_bufA);
    __half2* __restrict__     hout2 = reinterpret_cast<__half2*>(hout);

    const float tval = (MODE == 1) ? __ldg(&tarr[trow]) : 0.f;
    const int eg = lane >> 3;       // edge group 0..3
    const int f  = lane & 7;        // uint2 chunk (features 4f..4f+3)

    const int gwid = (blockIdx.x * blockDim.x + tid) >> 5;
    const int nw   = (gridDim.x * blockDim.x) >> 5;
    const uint32_t abase = (uint32_t)__cvta_generic_to_shared(&sA[w][0]);

    for (int nb = gwid * 16; nb < n; nb += nw * 16) {
        __syncwarp();                                   // WAR: prior ldmatrix vs new STS
        int rpi = nb + lane;
        if (rpi > n) rpi = n;
        int rp = __ldg(&g_rowptr[rpi]);                 // lanes 0..16 meaningful

#pragma unroll 1
        for (int i = 0; i < 16; i++) {
            int beg = __shfl_sync(0xffffffffu, rp, i);
            int end = __shfl_sync(0xffffffffu, rp, i + 1);
            float4 acc = make_float4(0.f, 0.f, 0.f, 0.f);
#pragma unroll 2
            for (int e = beg; e < end; e += 4) {
                int idx = e + eg;
                int safe = (idx < end) ? idx : (end - 1);
                unsigned long long v = __ldg(&g_edge[safe]);
                float wgt = (idx < end) ? __uint_as_float((unsigned)(v >> 32)) : 0.f;
                int src = (int)(unsigned)v;
                uint2 raw = __ldg(&hin[src * 8 + f]);
                float2 p0 = __half22float2(*reinterpret_cast<const __half2*>(&raw.x));
                float2 p1 = __half22float2(*reinterpret_cast<const __half2*>(&raw.y));
                acc.x = fmaf(wgt, p0.x, acc.x);
                acc.y = fmaf(wgt, p0.y, acc.y);
                acc.z = fmaf(wgt, p1.x, acc.z);
                acc.w = fmaf(wgt, p1.y, acc.w);
            }
#pragma unroll
            for (int off = 8; off <= 16; off <<= 1) {
                acc.x += __shfl_xor_sync(0xffffffffu, acc.x, off);
                acc.y += __shfl_xor_sync(0xffffffffu, acc.y, off);
                acc.z += __shfl_xor_sync(0xffffffffu, acc.z, off);
                acc.w += __shfl_xor_sync(0xffffffffu, acc.w, off);
            }
            if constexpr (MODE == 1) {
                if (f == 6) {                            // cols 26,27 <- ax, aone*t
                    float2 axw = __ldg(&g_axw[(nb + i < n) ? (nb + i) : 0]);
                    acc.z = axw.x;
                    acc.w = axw.y * tval;
                }
            }
            if (lane < 8) {
                uint2 pk;
                pk.x = packh2(acc.x, acc.y);
                pk.y = packh2(acc.z, acc.w);
                *reinterpret_cast<uint2*>(
                    reinterpret_cast<char*>(&sA[w][0]) + i * 80 + lane * 8) = pk;
            }
        }
        __syncwarp();                                   // RAW: STS -> ldmatrix

        // A fragments: af[kstep][4]
        uint32_t af[2][4];
#pragma unroll
        for (int s = 0; s < 2; s++) {
            int g2 = lane >> 3;
            uint32_t addr = abase + ((lane & 7) + (g2 & 1) * 8) * 80 + s * 32 + (g2 >> 1) * 16;
            asm volatile("ldmatrix.sync.aligned.m8n8.x4.shared.b16 {%0,%1,%2,%3},[%4];"
                         : "=r"(af[s][0]), "=r"(af[s][1]), "=r"(af[s][2]), "=r"(af[s][3])
                         : "r"(addr));
        }

        float c[4][4];
#pragma unroll
        for (int t = 0; t < 4; t++) {
            c[t][0] = biasr[t * 2];     c[t][1] = biasr[t * 2 + 1];
            c[t][2] = biasr[t * 2];     c[t][3] = biasr[t * 2 + 1];
        }
#pragma unroll
        for (int s = 0; s < 2; s++)
#pragma unroll
            for (int t = 0; t < 4; t++)
                mma16816(c[t], af[s], bf[s][t]);

        int r0 = nb + grp, r1 = nb + grp + 8;
        bool ok0 = r0 < n, ok1 = r1 < n;
#pragma unroll
        for (int t = 0; t < 4; t++) {
            c[t][0] = fmaxf(c[t][0], 0.f); c[t][1] = fmaxf(c[t][1], 0.f);
            c[t][2] = fmaxf(c[t][2], 0.f); c[t][3] = fmaxf(c[t][3], 0.f);
        }
#pragma unroll
        for (int t = 0; t < 4; t++) {
            __half2 p0 = __floats2half2_rn(c[t][0], c[t][1]);
            __half2 p1 = __floats2half2_rn(c[t][2], c[t][3]);
            if (ok0) hout2[r0 * 16 + t * 4 + tig] = p0;
            if (ok1) hout2[r1 * 16 + t * 4 + tig] = p1;
        }

        if constexpr (MODE == 3) {
            // h3 (relu'd C frags) ARE the A frags of the head MMA — no smem round-trip
            uint32_t ha[2][4];
            ha[0][0] = packh2(c[0][0], c[0][1]);  ha[0][1] = packh2(c[0][2], c[0][3]);
            ha[0][2] = packh2(c[1][0], c[1][1]);  ha[0][3] = packh2(c[1][2], c[1][3]);
            ha[1][0] = packh2(c[2][0], c[2][1]);  ha[1][1] = packh2(c[2][2], c[2][3]);
            ha[1][2] = packh2(c[3][0], c[3][1]);  ha[1][3] = packh2(c[3][2], c[3][3]);
            float z[4][4];
#pragma unroll
            for (int t = 0; t < 4; t++) {
                z[t][0] = b3r[t * 2];   z[t][1] = b3r[t * 2 + 1];
                z[t][2] = b3r[t * 2];   z[t][3] = b3r[t * 2 + 1];
            }
#pragma unroll
            for (int s = 0; s < 2; s++)
#pragma unroll
                for (int t = 0; t < 4; t++)
                    mma16816(z[t], ha[s], bf2[s][t]);
            float p0 = 0.f, p1 = 0.f;
#pragma unroll
            for (int t = 0; t < 4; t++) {
                p0 = fmaf(fmaxf(z[t][0], 0.f), wf4[t * 2],     p0);
                p0 = fmaf(fmaxf(z[t][1], 0.f), wf4[t * 2 + 1], p0);
                p1 = fmaf(fmaxf(z[t][2], 0.f), wf4[t * 2],     p1);
                p1 = fmaf(fmaxf(z[t][3], 0.f), wf4[t * 2 + 1], p1);
            }
            p0 += __shfl_xor_sync(0xffffffffu, p0, 1);
            p0 += __shfl_xor_sync(0xffffffffu, p0, 2);
            p1 += __shfl_xor_sync(0xffffffffu, p1, 1);
            p1 += __shfl_xor_sync(0xffffffffu, p1, 2);
            if (tig == 0) {
                long long ob = (long long)trow * n;
                if (ok0) out[ob + r0] = p0 + b4;
                if (ok1) out[ob + r1] = p1 + b4;
            }
        }
    }
}

// ---------------- launcher ----------------
extern "C" void kernel_launch(void* const* d_in, const int* in_sizes, int n_in,
                              void* d_out, int out_size) {
    const float* x    = (const float*)d_in[0];
    const float* t    = (const float*)d_in[1];
    const float* y    = (const float*)d_in[2];
    const int*   ei   = (const int*)d_in[3];     // int32 (JAX x64 disabled)
    const float* fc1W = (const float*)d_in[4],  *fc1b = (const float*)d_in[5];
    const float* fc2W = (const float*)d_in[6],  *fc2b = (const float*)d_in[7];
    const float* c1W  = (const float*)d_in[8],  *c1b  = (const float*)d_in[9];
    const float* c2W  = (const float*)d_in[10], *c2b  = (const float*)d_in[11];
    const float* c3W  = (const float*)d_in[12], *c3b  = (const float*)d_in[13];
    const float* fc3W = (const float*)d_in[14], *fc3b = (const float*)d_in[15];
    const float* fc4W = (const float*)d_in[16], *fc4b = (const float*)d_in[17];

    int n = in_sizes[0];          // N
    int T = in_sizes[1];          // timesteps
    int E = in_sizes[3] / 2;      // edges
    float* out = (float*)d_out;

    const int tb = 256;
    k_hist<<<(E + tb - 1) / tb, tb>>>(ei, E);                      // launch 1
    k_scan<<<1, 1024>>>(x, n);                                     // launch 2
    k_scatter_pre<<<(n + E + tb - 1) / tb, tb>>>(ei, E, x, y,      // launch 3
                                                 fc1W, fc1b, fc2W, fc2b, out, n);

    const int CB = 888;   // 148 SMs x 6 blocks of 128 threads
    for (int r = 1; r < T; r++) {                                  // launch 4 = conv1 (profiled)
        k_conv<1><<<CB, 128>>>(c1W, c1b, nullptr, nullptr, nullptr, nullptr, t, r, out, n);
        k_conv<2><<<CB, 128>>>(c2W, c2b, nullptr, nullptr, nullptr, nullptr, t, r, out, n);
        k_conv<3><<<CB, 128>>>(c3W, c3b, fc3W, fc3b, fc4W, fc4b, t, r, out, n);
    }
}

// round 8
// speedup vs baseline: 1.4880x; 1.4880x over previous
#include <cuda_runtime.h>
#include <cuda_fp16.h>
#include <cstdint>

#define NN 100000
#define EE 1600000
#define TOTE (NN + EE)

// ---------------- static device scratch (allocation-free, zero-init) ----------------
__device__ int                g_rowptr[NN + 1];
__device__ int                g_cnt[NN];          // histogram; reset by k_scan for next replay
__device__ int                g_cur[NN];          // scatter cursor
__device__ float              g_dis[NN];          // rsqrt(deg)
__device__ float2             g_axw[NN];          // {A_hat x, A_hat 1} per node (atomic-built)
__device__ unsigned long long g_edge[TOTE];       // packed {src(int32) | normbits<<32}
__device__ uint2              g_bufA[NN * 8];     // fp16 feature rows, 64B/node
__device__ uint2              g_bufB[NN * 8];
__device__ uint2              g_bufC[NN * 8];

__device__ __forceinline__ unsigned long long pack_edge(int c, float w) {
    return (unsigned long long)(unsigned)c |
           ((unsigned long long)__float_as_uint(w) << 32);
}

__device__ __forceinline__ uint32_t packh2(float a, float b) {
    __half2 h = __floats2half2_rn(a, b);
    return *reinterpret_cast<uint32_t*>(&h);
}

__device__ __forceinline__ void mma16816(float c[4], const uint32_t a[4], const uint32_t b[2]) {
    asm volatile("mma.sync.aligned.m16n8k16.row.col.f32.f16.f16.f32 "
                 "{%0,%1,%2,%3},{%4,%5,%6,%7},{%8,%9},{%0,%1,%2,%3};"
                 : "+f"(c[0]), "+f"(c[1]), "+f"(c[2]), "+f"(c[3])
                 : "r"(a[0]), "r"(a[1]), "r"(a[2]), "r"(a[3]), "r"(b[0]), "r"(b[1]));
}

// ---------------- preprocessing (3 launches so conv1 is launch #4) ----------------
__global__ void k_hist(const int* __restrict__ ei, int E) {
    int e = blockIdx.x * blockDim.x + threadIdx.x;
    if (e < E) atomicAdd(&g_cnt[ei[E + e]], 1);
}

__global__ void k_scan(const float* __restrict__ x, int n) {
    __shared__ int warpsum[32];
    __shared__ int chunkbase;
    const int tid = threadIdx.x, lane = tid & 31, wid = tid >> 5;
    if (tid == 0) chunkbase = 0;
    __syncthreads();
    for (int base = 0; base < n; base += 1024) {
        int i = base + tid;
        int ecnt = (i < n) ? g_cnt[i] : 0;
        if (i < n) g_cnt[i] = 0;                   // reset for next replay
        int v = ecnt + 1;                          // + self-loop
        int s = v;
#pragma unroll
        for (int d = 1; d < 32; d <<= 1) {
            int t = __shfl_up_sync(0xffffffffu, s, d);
            if (lane >= d) s += t;
        }
        if (lane == 31) warpsum[wid] = s;
        __syncthreads();
        if (wid == 0) {
            int ws = warpsum[lane];
#pragma unroll
            for (int d = 1; d < 32; d <<= 1) {
                int t = __shfl_up_sync(0xffffffffu, ws, d);
                if (lane >= d) ws += t;
            }
            warpsum[lane] = ws;
        }
        __syncthreads();
        int excl = chunkbase + s - v + (wid ? warpsum[wid - 1] : 0);
        if (i < n) {
            g_rowptr[i] = excl;
            float dv = rsqrtf((float)v);
            float dvdv = dv * dv;
            g_dis[i] = dv;
            g_edge[excl] = pack_edge(i, dvdv);     // self-loop edge first in row
            g_cur[i] = excl + 1;
            g_axw[i] = make_float2(dvdv * __ldg(&x[i]), dvdv);  // self-loop seed
        }
        __syncthreads();
        if (tid == 0) chunkbase += warpsum[31];
        __syncthreads();
    }
    if (tid == 0) g_rowptr[n] = chunkbase;
}

__global__ void k_scatter_pre(const int* __restrict__ ei, int E,
                              const float* __restrict__ x, const float* __restrict__ y,
                              const float* __restrict__ fc1W, const float* __restrict__ fc1b,
                              const float* __restrict__ fc2W, const float* __restrict__ fc2b,
                              float* __restrict__ out, int n) {
    __shared__ float s1W[32], s1b[32], s2W[32 * 26], s2b[26];
    for (int i = threadIdx.x; i < 32; i += blockDim.x) { s1W[i] = fc1W[i]; s1b[i] = fc1b[i]; }
    for (int i = threadIdx.x; i < 32 * 26; i += blockDim.x) s2W[i] = fc2W[i];
    for (int i = threadIdx.x; i < 26; i += blockDim.x) s2b[i] = fc2b[i];
    __syncthreads();
    int total = n + E;
    int stride = gridDim.x * blockDim.x;
    for (int g = blockIdx.x * blockDim.x + threadIdx.x; g < total; g += stride) {
        if (g < n) {
            int i = g;
            float y0 = y[i];
            out[i] = y0;
            float h0[32];
#pragma unroll
            for (int j = 0; j < 32; j++) h0[j] = fmaxf(fmaf(y0, s1W[j], s1b[j]), 0.f);
            __align__(8) __half hrow[32];
            for (int j = 0; j < 26; j++) {
                float s = s2b[j];
#pragma unroll
                for (int k = 0; k < 32; k++) s = fmaf(h0[k], s2W[k * 26 + j], s);
                hrow[j] = __float2half(fmaxf(s, 0.f));
            }
#pragma unroll
            for (int j = 26; j < 32; j++) hrow[j] = __float2half(0.f);
            const uint2* hr = reinterpret_cast<const uint2*>(hrow);
#pragma unroll
            for (int q = 0; q < 8; q++) g_bufA[i * 8 + q] = hr[q];
        } else {
            int e = g - n;
            int s = ei[e];
            int d = ei[E + e];
            float w = g_dis[s] * g_dis[d];
            int pos = atomicAdd(&g_cur[d], 1);
            g_edge[pos] = pack_edge(s, w);
            atomicAdd(&g_axw[d].x, w * __ldg(&x[s]));
            atomicAdd(&g_axw[d].y, w);
        }
    }
}

// ---------------- fused GCN conv: 16-node batches, edge-preload gather, HMMA epilogue ----------------
// MODE 1: agg cols 26/27 carry (A_hat x, A_hat 1 * t); W~ rows 26/27 = folded wx/wt.
// MODE 2: plain 32 -> 32.
// MODE 3: 32 -> 26 (cols padded 0) + fused fc3/relu/fc4 head via second MMA chain.
template <int MODE>
__global__ __launch_bounds__(256)
void k_conv(const float* __restrict__ W, const float* __restrict__ B,
            const float* __restrict__ f3W, const float* __restrict__ f3b,
            const float* __restrict__ f4W, const float* __restrict__ f4b,
            const float* __restrict__ tarr, int trow,
            float* __restrict__ out, int n) {
    constexpr int OUT = (MODE == 3) ? 26 : 32;
    constexpr unsigned FULL = 0xffffffffu;

    __shared__ __align__(16) __half sWt[32 * 40];   // W~ fp16, rows padded to 40 halves (80B)
    __shared__ __align__(16) __half sW2[32 * 40];   // fc3 padded (MODE 3 only)
    __shared__ __align__(16) __half sA[8][16 * 40]; // per-warp 16x32 agg tiles (1280B each)
    __shared__ float  sb[32];
    __shared__ float  sb3[32];
    __shared__ float  sf4[32];
    __shared__ float  sf4b;

    const int tid = threadIdx.x, lane = tid & 31, w = tid >> 5;

    for (int i = tid; i < 32 * 32; i += blockDim.x) {
        int k = i >> 5, j = i & 31;
        float v;
        if constexpr (MODE == 1) {
            if (k < 26)       v = W[k * 32 + j];
            else if (k == 26) v = W[26 * 32 + j] + W[27 * 32 + j] + W[28 * 32 + j];
            else if (k == 27) v = W[29 * 32 + j] + W[30 * 32 + j] + W[31 * 32 + j];
            else              v = 0.f;
        } else if constexpr (MODE == 2) {
            v = W[k * 32 + j];
        } else {
            v = (j < 26) ? W[k * 26 + j] : 0.f;
        }
        sWt[k * 40 + j] = __float2half(v);
        if constexpr (MODE == 3)
            sW2[k * 40 + j] = __float2half((k < 26) ? f3W[k * 32 + j] : 0.f);
    }
    for (int i = tid; i < 32; i += blockDim.x) {
        sb[i] = (i < OUT) ? B[i] : 0.f;
        if constexpr (MODE == 3) { sb3[i] = f3b[i]; sf4[i] = f4W[i]; }
    }
    if constexpr (MODE == 3) { if (tid == 0) sf4b = f4b[0]; }
    __syncthreads();

    // persistent B fragments: bf[kstep][ntile][2]
    uint32_t bf[2][4][2];
    uint32_t bf2[2][4][2];
    {
        int r = lane & 15;
#pragma unroll
        for (int s = 0; s < 2; s++)
#pragma unroll
            for (int t = 0; t < 4; t++) {
                uint32_t addr = (uint32_t)__cvta_generic_to_shared(&sWt[(s * 16 + r) * 40 + t * 8]);
                asm volatile("ldmatrix.sync.aligned.m8n8.x2.trans.shared.b16 {%0,%1},[%2];"
                             : "=r"(bf[s][t][0]), "=r"(bf[s][t][1]) : "r"(addr));
                if constexpr (MODE == 3) {
                    uint32_t a2 = (uint32_t)__cvta_generic_to_shared(&sW2[(s * 16 + r) * 40 + t * 8]);
                    asm volatile("ldmatrix.sync.aligned.m8n8.x2.trans.shared.b16 {%0,%1},[%2];"
                                 : "=r"(bf2[s][t][0]), "=r"(bf2[s][t][1]) : "r"(a2));
                }
            }
    }

    const int tig = lane & 3, grp = lane >> 2;
    float biasr[8];
#pragma unroll
    for (int t = 0; t < 4; t++) {
        biasr[t * 2]     = sb[t * 8 + tig * 2];
        biasr[t * 2 + 1] = sb[t * 8 + tig * 2 + 1];
    }
    float b3r[8], wf4[8], b4 = 0.f;
    if constexpr (MODE == 3) {
#pragma unroll
        for (int t = 0; t < 4; t++) {
            b3r[t * 2]     = sb3[t * 8 + tig * 2];
            b3r[t * 2 + 1] = sb3[t * 8 + tig * 2 + 1];
            wf4[t * 2]     = sf4[t * 8 + tig * 2];
            wf4[t * 2 + 1] = sf4[t * 8 + tig * 2 + 1];
        }
        b4 = sf4b;
    }

    const uint2* __restrict__ hin  = (MODE == 1) ? g_bufA : ((MODE == 2) ? g_bufB : g_bufC);
    uint2* __restrict__       hout = (MODE == 1) ? g_bufB : ((MODE == 2) ? g_bufC : g_bufA);
    __half2* __restrict__     hout2 = reinterpret_cast<__half2*>(hout);

    const float tval = (MODE == 1) ? __ldg(&tarr[trow]) : 0.f;
    const int eg = lane >> 3;       // edge group 0..3
    const int f  = lane & 7;        // uint2 chunk (features 4f..4f+3)

    const int gwid = (blockIdx.x * blockDim.x + tid) >> 5;
    const int nw   = (gridDim.x * blockDim.x) >> 5;
    const uint32_t abase = (uint32_t)__cvta_generic_to_shared(&sA[w][0]);

    for (int nb = gwid * 16; nb < n; nb += nw * 16) {
        __syncwarp();                                   // WAR: prior ldmatrix vs new STS
        int rpi = nb + lane;
        if (rpi > n) rpi = n;
        int rp = __ldg(&g_rowptr[rpi]);                 // lanes 0..16 meaningful

#pragma unroll 1
        for (int i = 0; i < 16; i++) {
            int beg = __shfl_sync(FULL, rp, i);
            int end = __shfl_sync(FULL, rp, i + 1);
            int deg = end - beg;
            // preload up to 32 edges with ONE warp-wide LDG; broadcast via shfl later
            int eidx = beg + lane;
            unsigned long long ev = __ldg(&g_edge[(eidx < end) ? eidx : (end - 1)]);
            float ew  = __uint_as_float((unsigned)(ev >> 32));
            int  esrc = (int)(unsigned)ev;
            int dlim = (deg < 32) ? deg : 32;

            float4 acc = make_float4(0.f, 0.f, 0.f, 0.f);
            // WARP-UNIFORM trip count (jb uniform); shfl executed by all lanes,
            // weight predicated to 0 for lanes whose j >= dlim.
#pragma unroll 2
            for (int jb = 0; jb < dlim; jb += 4) {
                int j = jb + eg;                        // per-lane edge index
                float wgt = __shfl_sync(FULL, ew, j & 31);
                int   src = __shfl_sync(FULL, esrc, j & 31);
                wgt = (j < dlim) ? wgt : 0.f;
                uint2 raw = __ldg(&hin[src * 8 + f]);
                float2 p0 = __half22float2(*reinterpret_cast<const __half2*>(&raw.x));
                float2 p1 = __half22float2(*reinterpret_cast<const __half2*>(&raw.y));
                acc.x = fmaf(wgt, p0.x, acc.x);
                acc.y = fmaf(wgt, p0.y, acc.y);
                acc.z = fmaf(wgt, p1.x, acc.z);
                acc.w = fmaf(wgt, p1.y, acc.w);
            }
            // rare tail: deg > 32 (no warp-sync primitives inside; divergence OK)
            for (int e2 = beg + 32 + eg; e2 < end; e2 += 4) {
                unsigned long long v = __ldg(&g_edge[e2]);
                float wgt = __uint_as_float((unsigned)(v >> 32));
                int   src = (int)(unsigned)v;
                uint2 raw = __ldg(&hin[src * 8 + f]);
                float2 p0 = __half22float2(*reinterpret_cast<const __half2*>(&raw.x));
                float2 p1 = __half22float2(*reinterpret_cast<const __half2*>(&raw.y));
                acc.x = fmaf(wgt, p0.x, acc.x);
                acc.y = fmaf(wgt, p0.y, acc.y);
                acc.z = fmaf(wgt, p1.x, acc.z);
                acc.w = fmaf(wgt, p1.y, acc.w);
            }
#pragma unroll
            for (int off = 8; off <= 16; off <<= 1) {
                acc.x += __shfl_xor_sync(FULL, acc.x, off);
                acc.y += __shfl_xor_sync(FULL, acc.y, off);
                acc.z += __shfl_xor_sync(FULL, acc.z, off);
                acc.w += __shfl_xor_sync(FULL, acc.w, off);
            }
            if constexpr (MODE == 1) {
                if (f == 6) {                            // cols 26,27 <- ax, aone*t
                    float2 axw = __ldg(&g_axw[(nb + i < n) ? (nb + i) : 0]);
                    acc.z = axw.x;
                    acc.w = axw.y * tval;
                }
            }
            if (lane < 8) {
                uint2 pk;
                pk.x = packh2(acc.x, acc.y);
                pk.y = packh2(acc.z, acc.w);
                *reinterpret_cast<uint2*>(
                    reinterpret_cast<char*>(&sA[w][0]) + i * 80 + lane * 8) = pk;
            }
        }
        __syncwarp();                                   // RAW: STS -> ldmatrix

        // A fragments: af[kstep][4]
        uint32_t af[2][4];
#pragma unroll
        for (int s = 0; s < 2; s++) {
            int g2 = lane >> 3;
            uint32_t addr = abase + ((lane & 7) + (g2 & 1) * 8) * 80 + s * 32 + (g2 >> 1) * 16;
            asm volatile("ldmatrix.sync.aligned.m8n8.x4.shared.b16 {%0,%1,%2,%3},[%4];"
                         : "=r"(af[s][0]), "=r"(af[s][1]), "=r"(af[s][2]), "=r"(af[s][3])
                         : "r"(addr));
        }

        float c[4][4];
#pragma unroll
        for (int t = 0; t < 4; t++) {
            c[t][0] = biasr[t * 2];     c[t][1] = biasr[t * 2 + 1];
            c[t][2] = biasr[t * 2];     c[t][3] = biasr[t * 2 + 1];
        }
#pragma unroll
        for (int s = 0; s < 2; s++)
#pragma unroll
            for (int t = 0; t < 4; t++)
                mma16816(c[t], af[s], bf[s][t]);

        int r0 = nb + grp, r1 = nb + grp + 8;
        bool ok0 = r0 < n, ok1 = r1 < n;
#pragma unroll
        for (int t = 0; t < 4; t++) {
            c[t][0] = fmaxf(c[t][0], 0.f); c[t][1] = fmaxf(c[t][1], 0.f);
            c[t][2] = fmaxf(c[t][2], 0.f); c[t][3] = fmaxf(c[t][3], 0.f);
        }
#pragma unroll
        for (int t = 0; t < 4; t++) {
            __half2 p0 = __floats2half2_rn(c[t][0], c[t][1]);
            __half2 p1 = __floats2half2_rn(c[t][2], c[t][3]);
            if (ok0) hout2[r0 * 16 + t * 4 + tig] = p0;
            if (ok1) hout2[r1 * 16 + t * 4 + tig] = p1;
        }

        if constexpr (MODE == 3) {
            // h3 (relu'd C frags) ARE the A frags of the head MMA — no smem round-trip
            uint32_t ha[2][4];
            ha[0][0] = packh2(c[0][0], c[0][1]);  ha[0][1] = packh2(c[0][2], c[0][3]);
            ha[0][2] = packh2(c[1][0], c[1][1]);  ha[0][3] = packh2(c[1][2], c[1][3]);
            ha[1][0] = packh2(c[2][0], c[2][1]);  ha[1][1] = packh2(c[2][2], c[2][3]);
            ha[1][2] = packh2(c[3][0], c[3][1]);  ha[1][3] = packh2(c[3][2], c[3][3]);
            float z[4][4];
#pragma unroll
            for (int t = 0; t < 4; t++) {
                z[t][0] = b3r[t * 2];   z[t][1] = b3r[t * 2 + 1];
                z[t][2] = b3r[t * 2];   z[t][3] = b3r[t * 2 + 1];
            }
#pragma unroll
            for (int s = 0; s < 2; s++)
#pragma unroll
                for (int t = 0; t < 4; t++)
                    mma16816(z[t], ha[s], bf2[s][t]);
            float p0 = 0.f, p1 = 0.f;
#pragma unroll
            for (int t = 0; t < 4; t++) {
                p0 = fmaf(fmaxf(z[t][0], 0.f), wf4[t * 2],     p0);
                p0 = fmaf(fmaxf(z[t][1], 0.f), wf4[t * 2 + 1], p0);
                p1 = fmaf(fmaxf(z[t][2], 0.f), wf4[t * 2],     p1);
                p1 = fmaf(fmaxf(z[t][3], 0.f), wf4[t * 2 + 1], p1);
            }
            p0 += __shfl_xor_sync(FULL, p0, 1);
            p0 += __shfl_xor_sync(FULL, p0, 2);
            p1 += __shfl_xor_sync(FULL, p1, 1);
            p1 += __shfl_xor_sync(FULL, p1, 2);
            if (tig == 0) {
                long long ob = (long long)trow * n;
                if (ok0) out[ob + r0] = p0 + b4;
                if (ok1) out[ob + r1] = p1 + b4;
            }
        }
    }
}

// ---------------- launcher ----------------
extern "C" void kernel_launch(void* const* d_in, const int* in_sizes, int n_in,
                              void* d_out, int out_size) {
    const float* x    = (const float*)d_in[0];
    const float* t    = (const float*)d_in[1];
    const float* y    = (const float*)d_in[2];
    const int*   ei   = (const int*)d_in[3];     // int32 (JAX x64 disabled)
    const float* fc1W = (const float*)d_in[4],  *fc1b = (const float*)d_in[5];
    const float* fc2W = (const float*)d_in[6],  *fc2b = (const float*)d_in[7];
    const float* c1W  = (const float*)d_in[8],  *c1b  = (const float*)d_in[9];
    const float* c2W  = (const float*)d_in[10], *c2b  = (const float*)d_in[11];
    const float* c3W  = (const float*)d_in[12], *c3b  = (const float*)d_in[13];
    const float* fc3W = (const float*)d_in[14], *fc3b = (const float*)d_in[15];
    const float* fc4W = (const float*)d_in[16], *fc4b = (const float*)d_in[17];

    int n = in_sizes[0];          // N
    int T = in_sizes[1];          // timesteps
    int E = in_sizes[3] / 2;      // edges
    float* out = (float*)d_out;

    const int tb = 256;
    k_hist<<<(E + tb - 1) / tb, tb>>>(ei, E);                      // launch 1
    k_scan<<<1, 1024>>>(x, n);                                     // launch 2
    k_scatter_pre<<<(n + E + tb - 1) / tb, tb>>>(ei, E, x, y,      // launch 3
                                                 fc1W, fc1b, fc2W, fc2b, out, n);

    const int CB = 592;   // 148 SMs x 4 blocks x 8 warps = 4736 warps = 64-reg residency cap
    for (int r = 1; r < T; r++) {                                  // launch 4 = conv1 (profiled)
        k_conv<1><<<CB, 256>>>(c1W, c1b, nullptr, nullptr, nullptr, nullptr, t, r, out, n);
        k_conv<2><<<CB, 256>>>(c2W, c2b, nullptr, nullptr, nullptr, nullptr, t, r, out, n);
        k_conv<3><<<CB, 256>>>(c3W, c3b, fc3W, fc3b, fc4W, fc4b, t, r, out, n);
    }
}